// round 7
// baseline (speedup 1.0000x reference)
#include <cuda_runtime.h>
#include <cuda_bf16.h>
#include <cstdint>
#include <math.h>

// ---------------- problem constants ----------------
#define NLAYER 4
#define HID    1024
#define BATCH  64
#define NSTEP  128
#define GATES  4096            // 4*HID
#define KTOT   2048            // x-part (1024) + h-part (1024)
#define BH     (BATCH * HID)

// ---------------- kernel config --------------------
#define NCTA   128             // 1 CTA per SM, <= 148 -> co-resident, barrier safe
#define NTHR   256             // 8 warps: 4 (M) x 2 (N) warp tiles of 16x16
#define NT     32              // permuted gate columns per CTA (8 h-cols x 4 gates)
#define KC     64              // K per pipeline chunk
#define NCHUNK (KTOT / KC)     // 32
#define NSTAGE 3
#define LDA    72              // padded smem row stride (bf16 elems) -> conflict-free ldmatrix
#define LDC    36              // gates smem row stride (floats), rows 16B aligned

// smem stage layout (bytes)
#define ST_AHI   0
#define ST_ALO   9216          // 64*72*2
#define ST_WHI   18432
#define ST_WLO   23040         // + 32*72*2
#define ST_BYTES 27648
#define SM_BIAS  (NSTAGE * ST_BYTES)               // 82944
#define SM_TOTAL (SM_BIAS + NLAYER * NT * 4)       // 83456

// ---------------- device scratch (allocation-free rule) ----------------
__device__ __nv_bfloat16 g_Whi[NLAYER][GATES][KTOT];   // [l][np][k], k contiguous (col-major B)
__device__ __nv_bfloat16 g_Wlo[NLAYER][GATES][KTOT];
__device__ __nv_bfloat16 g_Xhi[NSTEP][BATCH][HID];
__device__ __nv_bfloat16 g_Xlo[NSTEP][BATCH][HID];
__device__ __nv_bfloat16 g_Hhi[NLAYER][2][BATCH][HID]; // ping-pong on step parity
__device__ __nv_bfloat16 g_Hlo[NLAYER][2][BATCH][HID];
__device__ float         g_bias[NLAYER][GATES];        // permuted
__device__ unsigned      g_bar_cnt;
__device__ unsigned      g_bar_sense;

// =======================================================================
// conversion / init kernels (rerun each launch; deterministic)
// =======================================================================

// fp32 [l][k][4H] (Wi rows k<H, Wh rows k>=H) -> bf16 hi/lo, gate-permuted
// np = 4*(n mod H) + (n / H), transposed to [l][np][k].
__global__ void wconv_kernel(const float* __restrict__ Wi, const float* __restrict__ Wh) {
    __shared__ float s[32][33];
    int l  = blockIdx.z;
    int k0 = blockIdx.x * 32;
    int n0 = blockIdx.y * 32;
    int tx = threadIdx.x, ty = threadIdx.y;

    int k = k0 + ty, n = n0 + tx;
    const float* src = (k < HID)
        ? (Wi + ((size_t)l * HID + k) * GATES + n)
        : (Wh + ((size_t)l * HID + (k - HID)) * GATES + n);
    s[ty][tx] = *src;
    __syncthreads();

    // this thread now writes element (k = k0+tx, n = n0+ty)
    float v  = s[tx][ty];
    int   nn = n0 + ty;
    int   np = 4 * (nn & (HID - 1)) + (nn >> 10);
    __nv_bfloat16 hi = __float2bfloat16(v);
    __nv_bfloat16 lo = __float2bfloat16(v - __bfloat162float(hi));
    g_Whi[l][np][k0 + tx] = hi;
    g_Wlo[l][np][k0 + tx] = lo;
}

__global__ void iconv_kernel(const float* __restrict__ x) {
    size_t i = (size_t)blockIdx.x * blockDim.x + threadIdx.x;
    if (i < (size_t)NSTEP * BATCH * HID) {
        float v = x[i];
        __nv_bfloat16 hi = __float2bfloat16(v);
        __nv_bfloat16 lo = __float2bfloat16(v - __bfloat162float(hi));
        ((__nv_bfloat16*)g_Xhi)[i] = hi;
        ((__nv_bfloat16*)g_Xlo)[i] = lo;
    }
}

__global__ void minit_kernel(const float* __restrict__ b) {
    int i = blockIdx.x * blockDim.x + threadIdx.x;
    if (i < NLAYER * GATES) {
        int l  = i >> 12;
        int n  = i & (GATES - 1);
        int np = 4 * (n & (HID - 1)) + (n >> 10);
        g_bias[l][np] = b[i];
    }
    const int hn = NLAYER * 2 * BATCH * HID;
    for (int j = i; j < hn; j += gridDim.x * blockDim.x) {
        ((__nv_bfloat16*)g_Hhi)[j] = __float2bfloat16(0.f);
        ((__nv_bfloat16*)g_Hlo)[j] = __float2bfloat16(0.f);
    }
    if (i == 0) { g_bar_cnt = 0; g_bar_sense = 0; }
}

// =======================================================================
// persistent LSTM kernel
// =======================================================================

__device__ __forceinline__ void cp16(uint32_t dst, const void* src) {
    asm volatile("cp.async.cg.shared.global [%0], [%1], 16;\n" :: "r"(dst), "l"(src));
}
__device__ __forceinline__ void cp_commit() { asm volatile("cp.async.commit_group;\n"); }
template <int N> __device__ __forceinline__ void cp_wait() {
    asm volatile("cp.async.wait_group %0;\n" :: "n"(N));
}
__device__ __forceinline__ void ldsm4(uint32_t* r, uint32_t addr) {
    asm volatile("ldmatrix.sync.aligned.m8n8.x4.shared.b16 {%0,%1,%2,%3}, [%4];\n"
                 : "=r"(r[0]), "=r"(r[1]), "=r"(r[2]), "=r"(r[3]) : "r"(addr));
}
__device__ __forceinline__ void mma16816(float* c, const uint32_t* a, const uint32_t* b) {
    asm volatile(
        "mma.sync.aligned.m16n8k16.row.col.f32.bf16.bf16.f32 "
        "{%0,%1,%2,%3}, {%4,%5,%6,%7}, {%8,%9}, {%0,%1,%2,%3};\n"
        : "+f"(c[0]), "+f"(c[1]), "+f"(c[2]), "+f"(c[3])
        : "r"(a[0]), "r"(a[1]), "r"(a[2]), "r"(a[3]), "r"(b[0]), "r"(b[1]));
}

__device__ __forceinline__ void grid_sync(unsigned nbar) {
    __threadfence();
    __syncthreads();
    if (threadIdx.x == 0) {
        if (atomicAdd(&g_bar_cnt, 1) == NCTA - 1) {
            g_bar_cnt = 0;
            __threadfence();
            atomicExch(&g_bar_sense, nbar);
        } else {
            while (*(volatile unsigned*)&g_bar_sense < nbar) __nanosleep(64);
            __threadfence();
        }
    }
    __syncthreads();
}

// 1536 x 16B units per chunk: A hi/lo (2*64 rows * 8 segs) + W hi/lo (2*32 rows * 8 segs)
__device__ __forceinline__ void load_chunk(
    uint32_t stg, int kg0,
    const __nv_bfloat16* __restrict__ A1h, const __nv_bfloat16* __restrict__ A1l,
    const __nv_bfloat16* __restrict__ A2h, const __nv_bfloat16* __restrict__ A2l,
    const __nv_bfloat16* __restrict__ Wh_, const __nv_bfloat16* __restrict__ Wl_,
    int tid)
{
    const __nv_bfloat16* Ah; const __nv_bfloat16* Al; int ko;
    if (kg0 < HID) { Ah = A1h; Al = A1l; ko = kg0; }
    else           { Ah = A2h; Al = A2l; ko = kg0 - HID; }
#pragma unroll
    for (int ii = 0; ii < 6; ii++) {
        int u = tid + ii * NTHR;
        if (u < 1024) {
            int plane = u >> 9, v = u & 511, row = v >> 3, seg = v & 7;
            const __nv_bfloat16* src = (plane ? Al : Ah) + row * HID + ko + seg * 8;
            uint32_t dst = stg + (plane ? ST_ALO : ST_AHI) + (uint32_t)(row * LDA + seg * 8) * 2;
            cp16(dst, src);
        } else {
            int w = u - 1024;
            int plane = w >> 8, v = w & 255, row = v >> 3, seg = v & 7;
            const __nv_bfloat16* src = (plane ? Wl_ : Wh_) + row * KTOT + kg0 + seg * 8;
            uint32_t dst = stg + (plane ? ST_WLO : ST_WHI) + (uint32_t)(row * LDA + seg * 8) * 2;
            cp16(dst, src);
        }
    }
}

__device__ __forceinline__ float sigmoidf_(float x) { return 1.f / (1.f + expf(-x)); }

__global__ void __launch_bounds__(NTHR, 1)
lstm_main(float* __restrict__ out, int out_floats) {
    extern __shared__ char smem[];
    const uint32_t sbase = (uint32_t)__cvta_generic_to_shared(smem);
    const int tid  = threadIdx.x;
    const int bid  = blockIdx.x;
    const int lane = tid & 31, warp = tid >> 5;
    const int mi = warp & 3, nj = warp >> 2;     // warp tile: rows 16*mi, cols 16*nj
    const int np0 = bid * NT;

    float* bias_s = (float*)(smem + SM_BIAS);
    for (int i = tid; i < NLAYER * NT; i += NTHR)
        bias_s[i] = g_bias[i >> 5][np0 + (i & 31)];

    float cst[NLAYER][2];
#pragma unroll
    for (int a = 0; a < NLAYER; a++) { cst[a][0] = 0.f; cst[a][1] = 0.f; }

    // cell-update mapping: thread owns pairs p=2*tid, 2*tid+1 -> (row_u, hc), (row_u, hc+1)
    const int p0 = 2 * tid, row_u = p0 >> 3, hc = p0 & 7;   // hc even
    const int colg = 8 * bid + hc;

    __syncthreads();
    unsigned nbar = 0;

    for (int t = 0; t < NSTEP; t++) {
        const int par = t & 1, prv = par ^ 1;
        for (int l = 0; l < NLAYER; l++) {
            const __nv_bfloat16* A1h = (l == 0) ? &g_Xhi[t][0][0] : &g_Hhi[l - 1][par][0][0];
            const __nv_bfloat16* A1l = (l == 0) ? &g_Xlo[t][0][0] : &g_Hlo[l - 1][par][0][0];
            const __nv_bfloat16* A2h = &g_Hhi[l][prv][0][0];
            const __nv_bfloat16* A2l = &g_Hlo[l][prv][0][0];
            const __nv_bfloat16* Wh_ = &g_Whi[l][np0][0];
            const __nv_bfloat16* Wl_ = &g_Wlo[l][np0][0];

            float acc0[4] = {0.f, 0.f, 0.f, 0.f};
            float acc1[4] = {0.f, 0.f, 0.f, 0.f};

            load_chunk(sbase + 0 * ST_BYTES, 0 * KC, A1h, A1l, A2h, A2l, Wh_, Wl_, tid); cp_commit();
            load_chunk(sbase + 1 * ST_BYTES, 1 * KC, A1h, A1l, A2h, A2l, Wh_, Wl_, tid); cp_commit();

            for (int c = 0; c < NCHUNK; c++) {
                if (c < NCHUNK - 1) cp_wait<1>(); else cp_wait<0>();
                __syncthreads();
                if (c + 2 < NCHUNK) {
                    load_chunk(sbase + (uint32_t)((c + 2) % NSTAGE) * ST_BYTES, (c + 2) * KC,
                               A1h, A1l, A2h, A2l, Wh_, Wl_, tid);
                    cp_commit();
                }
                uint32_t stg = sbase + (uint32_t)(c % NSTAGE) * ST_BYTES;
#pragma unroll
                for (int kk = 0; kk < 4; kk++) {
                    uint32_t arow = mi * 16 + (lane & 15);
                    uint32_t acol = kk * 16 + (lane >> 4) * 8;
                    uint32_t aaddr = stg + ST_AHI + (arow * LDA + acol) * 2;
                    uint32_t ah[4], al[4], bh[4], bl[4];
                    ldsm4(ah, aaddr);
                    ldsm4(al, aaddr + (ST_ALO - ST_AHI));
                    uint32_t brow = nj * 16 + (lane & 7) + ((lane >> 4) & 1) * 8;
                    uint32_t bcol = kk * 16 + ((lane >> 3) & 1) * 8;
                    uint32_t baddr = stg + ST_WHI + (brow * LDA + bcol) * 2;
                    ldsm4(bh, baddr);
                    ldsm4(bl, baddr + (ST_WLO - ST_WHI));
                    mma16816(acc0, ah, bh);     mma16816(acc1, ah, bh + 2);
                    mma16816(acc0, ah, bl);     mma16816(acc1, ah, bl + 2);
                    mma16816(acc0, al, bh);     mma16816(acc1, al, bh + 2);
                }
            }

            // dump gate accumulators to smem (overlaps stage 0; all cp.async drained)
            float* gs = (float*)smem;
            {
                int r0 = mi * 16 + (lane >> 2);
                int c0 = nj * 16 + (lane & 3) * 2;
                *(float2*)&gs[(r0    ) * LDC + c0    ] = make_float2(acc0[0], acc0[1]);
                *(float2*)&gs[(r0 + 8) * LDC + c0    ] = make_float2(acc0[2], acc0[3]);
                *(float2*)&gs[(r0    ) * LDC + c0 + 8] = make_float2(acc1[0], acc1[1]);
                *(float2*)&gs[(r0 + 8) * LDC + c0 + 8] = make_float2(acc1[2], acc1[3]);
            }
            __syncthreads();

            // cell update: this thread owns h columns (colg, colg+1) for row row_u
            {
                float4 gv0 = *(const float4*)&gs[row_u * LDC + 4 * hc];
                float4 gv1 = *(const float4*)&gs[row_u * LDC + 4 * hc + 4];
                float4 bb0 = *(const float4*)&bias_s[l * NT + 4 * hc];
                float4 bb1 = *(const float4*)&bias_s[l * NT + 4 * hc + 4];

                float i0 = gv0.x + bb0.x, f0 = gv0.y + bb0.y, gg0 = gv0.z + bb0.z, o0 = gv0.w + bb0.w;
                float i1 = gv1.x + bb1.x, f1 = gv1.y + bb1.y, gg1 = gv1.z + bb1.z, o1 = gv1.w + bb1.w;

                float cn0 = sigmoidf_(f0) * cst[l][0] + sigmoidf_(i0) * tanhf(gg0);
                float cn1 = sigmoidf_(f1) * cst[l][1] + sigmoidf_(i1) * tanhf(gg1);
                cst[l][0] = cn0; cst[l][1] = cn1;
                float h0 = sigmoidf_(o0) * tanhf(cn0);
                float h1 = sigmoidf_(o1) * tanhf(cn1);

                __nv_bfloat16 h0h = __float2bfloat16(h0);
                __nv_bfloat16 h1h = __float2bfloat16(h1);
                __nv_bfloat16 h0l = __float2bfloat16(h0 - __bfloat162float(h0h));
                __nv_bfloat16 h1l = __float2bfloat16(h1 - __bfloat162float(h1h));
                g_Hhi[l][par][row_u][colg]     = h0h;
                g_Hhi[l][par][row_u][colg + 1] = h1h;
                g_Hlo[l][par][row_u][colg]     = h0l;
                g_Hlo[l][par][row_u][colg + 1] = h1l;

                if (l == NLAYER - 1 && t == NSTEP - 1) {
                    int idx = row_u * HID + colg;
                    out[idx] = h0; out[idx + 1] = h1;                       // output
                    if (out_floats >= 2 * BH) { out[BH + idx] = h0; out[BH + idx + 1] = h1; }       // h final
                    if (out_floats >= 3 * BH) { out[2 * BH + idx] = cn0; out[2 * BH + idx + 1] = cn1; } // c final
                }
            }

            nbar++;
            grid_sync(nbar);
        }
    }
}

// =======================================================================
// launch
// =======================================================================
extern "C" void kernel_launch(void* const* d_in, const int* in_sizes, int n_in,
                              void* d_out, int out_size) {
    const float* x  = (const float*)d_in[0];
    const float* Wi = (const float*)d_in[1];
    const float* Wh = (const float*)d_in[2];
    const float* b  = (const float*)d_in[3];
    float* out = (float*)d_out;

    cudaFuncSetAttribute(lstm_main, cudaFuncAttributeMaxDynamicSharedMemorySize, SM_TOTAL);

    minit_kernel<<<64, 256>>>(b);
    wconv_kernel<<<dim3(KTOT / 32, GATES / 32, NLAYER), dim3(32, 32)>>>(Wi, Wh);
    iconv_kernel<<<(NSTEP * BATCH * HID + 255) / 256, 256>>>(x);
    lstm_main<<<NCTA, NTHR, SM_TOTAL>>>(out, out_size);
}

// round 10
// speedup vs baseline: 1.2032x; 1.2032x over previous
#include <cuda_runtime.h>
#include <cuda_bf16.h>
#include <cstdint>
#include <math.h>

// ---------------- problem constants ----------------
#define NLAYER 4
#define HID    1024
#define BATCH  64
#define NSTEP  128
#define GATES  4096            // 4*HID
#define KTOT   2048            // x-part (1024) + h-part (1024)
#define BH     (BATCH * HID)

// ---------------- kernel config --------------------
#define NCTA   128             // 1 CTA per SM, <= 148 -> co-resident, barrier safe
#define NTHR   512             // 16 warps: 2 (K-split) x [4 (M) x 2 (N)] tiles of 16x16
#define NT     32              // permuted gate columns per CTA (8 h-cols x 4 gates)
#define KC     64              // K per pipeline chunk
#define NCHUNK (KTOT / KC)     // 32
#define NSTAGE 3
#define LDA    72              // padded smem row stride (bf16 elems) -> conflict-free ldmatrix
#define LDC    36              // gates smem row stride (floats), rows 16B aligned

// smem stage layout (bytes)
#define ST_AHI   0
#define ST_ALO   9216          // 64*72*2
#define ST_WHI   18432
#define ST_WLO   23040         // + 32*72*2
#define ST_BYTES 27648
// gate buffers (post-K-loop) overlap stage 0: 2 x 9216 = 18432 <= 27648
#define SM_GS0   0
#define SM_GS1   9216
#define SM_BIAS  (NSTAGE * ST_BYTES)               // 82944
#define SM_TOTAL (SM_BIAS + NLAYER * NT * 4)       // 83456

// ---------------- device scratch (allocation-free rule) ----------------
__device__ __nv_bfloat16 g_Whi[NLAYER][GATES][KTOT];   // [l][np][k], k contiguous (col-major B)
__device__ __nv_bfloat16 g_Wlo[NLAYER][GATES][KTOT];
__device__ __nv_bfloat16 g_Xhi[NSTEP][BATCH][HID];
__device__ __nv_bfloat16 g_Xlo[NSTEP][BATCH][HID];
__device__ __nv_bfloat16 g_Hhi[NLAYER][2][BATCH][HID]; // ping-pong on step parity
__device__ __nv_bfloat16 g_Hlo[NLAYER][2][BATCH][HID];
__device__ float         g_bias[NLAYER][GATES];        // permuted
__device__ unsigned      g_bar_cnt;
__device__ unsigned      g_bar_sense;

// =======================================================================
// conversion / init kernels (rerun each launch; deterministic)
// =======================================================================

__global__ void wconv_kernel(const float* __restrict__ Wi, const float* __restrict__ Wh) {
    __shared__ float s[32][33];
    int l  = blockIdx.z;
    int k0 = blockIdx.x * 32;
    int n0 = blockIdx.y * 32;
    int tx = threadIdx.x, ty = threadIdx.y;

    int k = k0 + ty, n = n0 + tx;
    const float* src = (k < HID)
        ? (Wi + ((size_t)l * HID + k) * GATES + n)
        : (Wh + ((size_t)l * HID + (k - HID)) * GATES + n);
    s[ty][tx] = *src;
    __syncthreads();

    float v  = s[tx][ty];
    int   nn = n0 + ty;
    int   np = 4 * (nn & (HID - 1)) + (nn >> 10);
    __nv_bfloat16 hi = __float2bfloat16(v);
    __nv_bfloat16 lo = __float2bfloat16(v - __bfloat162float(hi));
    g_Whi[l][np][k0 + tx] = hi;
    g_Wlo[l][np][k0 + tx] = lo;
}

__global__ void iconv_kernel(const float* __restrict__ x) {
    size_t i = (size_t)blockIdx.x * blockDim.x + threadIdx.x;
    if (i < (size_t)NSTEP * BATCH * HID) {
        float v = x[i];
        __nv_bfloat16 hi = __float2bfloat16(v);
        __nv_bfloat16 lo = __float2bfloat16(v - __bfloat162float(hi));
        ((__nv_bfloat16*)g_Xhi)[i] = hi;
        ((__nv_bfloat16*)g_Xlo)[i] = lo;
    }
}

__global__ void minit_kernel(const float* __restrict__ b) {
    int i = blockIdx.x * blockDim.x + threadIdx.x;
    if (i < NLAYER * GATES) {
        int l  = i >> 12;
        int n  = i & (GATES - 1);
        int np = 4 * (n & (HID - 1)) + (n >> 10);
        g_bias[l][np] = b[i];
    }
    const int hn = NLAYER * 2 * BATCH * HID;
    for (int j = i; j < hn; j += gridDim.x * blockDim.x) {
        ((__nv_bfloat16*)g_Hhi)[j] = __float2bfloat16(0.f);
        ((__nv_bfloat16*)g_Hlo)[j] = __float2bfloat16(0.f);
    }
    if (i == 0) { g_bar_cnt = 0; g_bar_sense = 0; }
}

// =======================================================================
// persistent LSTM kernel
// =======================================================================

__device__ __forceinline__ void cp16(uint32_t dst, const void* src) {
    asm volatile("cp.async.cg.shared.global [%0], [%1], 16;\n" :: "r"(dst), "l"(src));
}
__device__ __forceinline__ void cp_commit() { asm volatile("cp.async.commit_group;\n"); }
template <int N> __device__ __forceinline__ void cp_wait() {
    asm volatile("cp.async.wait_group %0;\n" :: "n"(N));
}
__device__ __forceinline__ void ldsm4(uint32_t* r, uint32_t addr) {
    asm volatile("ldmatrix.sync.aligned.m8n8.x4.shared.b16 {%0,%1,%2,%3}, [%4];\n"
                 : "=r"(r[0]), "=r"(r[1]), "=r"(r[2]), "=r"(r[3]) : "r"(addr));
}
__device__ __forceinline__ void mma16816(float* c, const uint32_t* a, const uint32_t* b) {
    asm volatile(
        "mma.sync.aligned.m16n8k16.row.col.f32.bf16.bf16.f32 "
        "{%0,%1,%2,%3}, {%4,%5,%6,%7}, {%8,%9}, {%0,%1,%2,%3};\n"
        : "+f"(c[0]), "+f"(c[1]), "+f"(c[2]), "+f"(c[3])
        : "r"(a[0]), "r"(a[1]), "r"(a[2]), "r"(a[3]), "r"(b[0]), "r"(b[1]));
}

__device__ __forceinline__ void grid_sync(unsigned nbar) {
    __threadfence();
    __syncthreads();
    if (threadIdx.x == 0) {
        if (atomicAdd(&g_bar_cnt, 1) == NCTA - 1) {
            g_bar_cnt = 0;
            __threadfence();
            atomicExch(&g_bar_sense, nbar);
        } else {
            while (*(volatile unsigned*)&g_bar_sense < nbar) __nanosleep(64);
            __threadfence();
        }
    }
    __syncthreads();
}

// 1536 x 16B units per chunk: A hi/lo (2*64 rows * 8 segs) + W hi/lo (2*32 rows * 8 segs)
__device__ __forceinline__ void load_chunk(
    uint32_t stg, int kg0,
    const __nv_bfloat16* __restrict__ A1h, const __nv_bfloat16* __restrict__ A1l,
    const __nv_bfloat16* __restrict__ A2h, const __nv_bfloat16* __restrict__ A2l,
    const __nv_bfloat16* __restrict__ Wh_, const __nv_bfloat16* __restrict__ Wl_,
    int tid)
{
    const __nv_bfloat16* Ah; const __nv_bfloat16* Al; int ko;
    if (kg0 < HID) { Ah = A1h; Al = A1l; ko = kg0; }
    else           { Ah = A2h; Al = A2l; ko = kg0 - HID; }
#pragma unroll
    for (int ii = 0; ii < 3; ii++) {
        int u = tid + ii * NTHR;
        if (u < 1024) {
            int plane = u >> 9, v = u & 511, row = v >> 3, seg = v & 7;
            const __nv_bfloat16* src = (plane ? Al : Ah) + row * HID + ko + seg * 8;
            uint32_t dst = stg + (plane ? ST_ALO : ST_AHI) + (uint32_t)(row * LDA + seg * 8) * 2;
            cp16(dst, src);
        } else {
            int w = u - 1024;
            int plane = w >> 8, v = w & 255, row = v >> 3, seg = v & 7;
            const __nv_bfloat16* src = (plane ? Wl_ : Wh_) + row * KTOT + kg0 + seg * 8;
            uint32_t dst = stg + (plane ? ST_WLO : ST_WHI) + (uint32_t)(row * LDA + seg * 8) * 2;
            cp16(dst, src);
        }
    }
}

__device__ __forceinline__ float sigmoidf_(float x) { return 1.f / (1.f + expf(-x)); }

__global__ void __launch_bounds__(NTHR, 1)
lstm_main(float* __restrict__ out, int out_floats) {
    extern __shared__ char smem[];
    const uint32_t sbase = (uint32_t)__cvta_generic_to_shared(smem);
    const int tid  = threadIdx.x;
    const int bid  = blockIdx.x;
    const int lane = tid & 31, warp = tid >> 5;
    const int ki   = warp & 1;                   // K-half: kk in {2*ki, 2*ki+1}
    const int wsub = warp >> 1;                  // 0..7
    const int mi = wsub & 3, nj = wsub >> 2;     // warp tile: rows 16*mi, cols 16*nj
    const int np0 = bid * NT;

    float* bias_s = (float*)(smem + SM_BIAS);
    for (int i = tid; i < NLAYER * NT; i += NTHR)
        bias_s[i] = g_bias[i >> 5][np0 + (i & 31)];

    float cst[NLAYER];
#pragma unroll
    for (int a = 0; a < NLAYER; a++) cst[a] = 0.f;

    // cell-update mapping: thread owns h element (row_u, hc)
    const int row_u = tid >> 3, hc = tid & 7;
    const int colg  = 8 * bid + hc;

    __syncthreads();
    unsigned nbar = 0;

    for (int t = 0; t < NSTEP; t++) {
        const int par = t & 1, prv = par ^ 1;
        for (int l = 0; l < NLAYER; l++) {
            const __nv_bfloat16* A1h = (l == 0) ? &g_Xhi[t][0][0] : &g_Hhi[l - 1][par][0][0];
            const __nv_bfloat16* A1l = (l == 0) ? &g_Xlo[t][0][0] : &g_Hlo[l - 1][par][0][0];
            const __nv_bfloat16* A2h = &g_Hhi[l][prv][0][0];
            const __nv_bfloat16* A2l = &g_Hlo[l][prv][0][0];
            const __nv_bfloat16* Wh_ = &g_Whi[l][np0][0];
            const __nv_bfloat16* Wl_ = &g_Wlo[l][np0][0];

            float acc0[4] = {0.f, 0.f, 0.f, 0.f};
            float acc1[4] = {0.f, 0.f, 0.f, 0.f};

            load_chunk(sbase + 0 * ST_BYTES, 0 * KC, A1h, A1l, A2h, A2l, Wh_, Wl_, tid); cp_commit();
            load_chunk(sbase + 1 * ST_BYTES, 1 * KC, A1h, A1l, A2h, A2l, Wh_, Wl_, tid); cp_commit();

            for (int c = 0; c < NCHUNK; c++) {
                if (c < NCHUNK - 1) cp_wait<1>(); else cp_wait<0>();
                __syncthreads();
                if (c + 2 < NCHUNK) {
                    load_chunk(sbase + (uint32_t)((c + 2) % NSTAGE) * ST_BYTES, (c + 2) * KC,
                               A1h, A1l, A2h, A2l, Wh_, Wl_, tid);
                    cp_commit();
                }
                uint32_t stg = sbase + (uint32_t)(c % NSTAGE) * ST_BYTES;
#pragma unroll
                for (int j = 0; j < 2; j++) {
                    int kk = ki * 2 + j;
                    uint32_t arow = mi * 16 + (lane & 15);
                    uint32_t acol = kk * 16 + (lane >> 4) * 8;
                    uint32_t aaddr = stg + ST_AHI + (arow * LDA + acol) * 2;
                    uint32_t ah[4], al[4], bh[4], bl[4];
                    ldsm4(ah, aaddr);
                    ldsm4(al, aaddr + (ST_ALO - ST_AHI));
                    uint32_t brow = nj * 16 + (lane & 7) + ((lane >> 4) & 1) * 8;
                    uint32_t bcol = kk * 16 + ((lane >> 3) & 1) * 8;
                    uint32_t baddr = stg + ST_WHI + (brow * LDA + bcol) * 2;
                    ldsm4(bh, baddr);
                    ldsm4(bl, baddr + (ST_WLO - ST_WHI));
                    mma16816(acc0, ah, bh);     mma16816(acc1, ah, bh + 2);
                    mma16816(acc0, ah, bl);     mma16816(acc1, ah, bl + 2);
                    mma16816(acc0, al, bh);     mma16816(acc1, al, bh + 2);
                }
            }

            // dump partial gate accumulators to the two K-half smem buffers
            float* gs = (float*)(smem + (ki ? SM_GS1 : SM_GS0));
            {
                int r0 = mi * 16 + (lane >> 2);
                int c0 = nj * 16 + (lane & 3) * 2;
                *(float2*)&gs[(r0    ) * LDC + c0    ] = make_float2(acc0[0], acc0[1]);
                *(float2*)&gs[(r0 + 8) * LDC + c0    ] = make_float2(acc0[2], acc0[3]);
                *(float2*)&gs[(r0    ) * LDC + c0 + 8] = make_float2(acc1[0], acc1[1]);
                *(float2*)&gs[(r0 + 8) * LDC + c0 + 8] = make_float2(acc1[2], acc1[3]);
            }
            __syncthreads();

            // cell update: this thread owns h column colg for row row_u
            {
                const float* g0 = (const float*)(smem + SM_GS0);
                const float* g1 = (const float*)(smem + SM_GS1);
                float4 p0 = *(const float4*)&g0[row_u * LDC + 4 * hc];
                float4 p1 = *(const float4*)&g1[row_u * LDC + 4 * hc];
                float4 bb = *(const float4*)&bias_s[l * NT + 4 * hc];

                float i0 = p0.x + p1.x + bb.x;
                float f0 = p0.y + p1.y + bb.y;
                float gg = p0.z + p1.z + bb.z;
                float o0 = p0.w + p1.w + bb.w;

                float cn = sigmoidf_(f0) * cst[l] + sigmoidf_(i0) * tanhf(gg);
                cst[l] = cn;
                float h = sigmoidf_(o0) * tanhf(cn);

                __nv_bfloat16 hh = __float2bfloat16(h);
                __nv_bfloat16 hl = __float2bfloat16(h - __bfloat162float(hh));
                g_Hhi[l][par][row_u][colg] = hh;
                g_Hlo[l][par][row_u][colg] = hl;

                if (l == NLAYER - 1 && t == NSTEP - 1) {
                    int idx = row_u * HID + colg;
                    out[idx] = h;                                           // output
                    if (out_floats >= 2 * BH) out[BH + idx] = h;            // h final
                    if (out_floats >= 3 * BH) out[2 * BH + idx] = cn;       // c final
                }
            }

            nbar++;
            grid_sync(nbar);
        }
    }
}

// =======================================================================
// launch
// =======================================================================
extern "C" void kernel_launch(void* const* d_in, const int* in_sizes, int n_in,
                              void* d_out, int out_size) {
    const float* x  = (const float*)d_in[0];
    const float* Wi = (const float*)d_in[1];
    const float* Wh = (const float*)d_in[2];
    const float* b  = (const float*)d_in[3];
    float* out = (float*)d_out;

    cudaFuncSetAttribute(lstm_main, cudaFuncAttributeMaxDynamicSharedMemorySize, SM_TOTAL);

    minit_kernel<<<64, 256>>>(b);
    wconv_kernel<<<dim3(KTOT / 32, GATES / 32, NLAYER), dim3(32, 32)>>>(Wi, Wh);
    iconv_kernel<<<(NSTEP * BATCH * HID + 255) / 256, 256>>>(x);
    lstm_main<<<NCTA, NTHR, SM_TOTAL>>>(out, out_size);
}

// round 12
// speedup vs baseline: 1.3852x; 1.1513x over previous
#include <cuda_runtime.h>
#include <cuda_bf16.h>
#include <cstdint>
#include <math.h>

// ---------------- problem constants ----------------
#define NLAYER 4
#define HID    1024
#define BATCH  64
#define NSTEP  128
#define GATES  4096            // 4*HID
#define KTOT   2048            // x-part (1024) + h-part (1024)
#define BH     (BATCH * HID)

// ---------------- kernel config --------------------
#define NCTA   128             // 1 CTA per SM, co-resident -> grid barrier safe
#define NTHR   512             // 16 warps: 2 (M-split, m32) x 8 (K-split, k16 each)
#define NT     32              // permuted gate columns per CTA (8 h-cols x 4 gates)
#define KC     128             // K per pipeline chunk
#define NCHUNK (KTOT / KC)     // 16
#define NSTAGE 3
#define LDA    136             // padded smem row stride (bf16) -> conflict-free ldsm
#define LDC    36              // gates smem row stride (floats)

// smem stage layout (bytes)
#define ST_AHI   0
#define ST_ALO   17408         // 64*136*2
#define ST_WHI   34816
#define ST_WLO   43520         // + 32*136*2
#define ST_BYTES 52224
// 8 gate partial buffers (64 x 36 floats = 9216 B each) live in stages 1..2,
// which are dead after the wait<0> + syncthreads at the last chunk (reads stage 0).
#define SM_GATES ST_BYTES                          // [52224, 125952) in stages 1-2
#define SM_BIAS  (NSTAGE * ST_BYTES)               // 156672
#define SM_TOTAL (SM_BIAS + NLAYER * NT * 4)       // 157184

// ---------------- device scratch (allocation-free rule) ----------------
__device__ __nv_bfloat16 g_Whi[NLAYER][GATES][KTOT];   // [l][np][k], k contiguous
__device__ __nv_bfloat16 g_Wlo[NLAYER][GATES][KTOT];
__device__ __nv_bfloat16 g_Xhi[NSTEP][BATCH][HID];
__device__ __nv_bfloat16 g_Xlo[NSTEP][BATCH][HID];
__device__ __nv_bfloat16 g_Hhi[NLAYER][2][BATCH][HID]; // ping-pong on step parity
__device__ __nv_bfloat16 g_Hlo[NLAYER][2][BATCH][HID];
__device__ float         g_bias[NLAYER][GATES];        // permuted
__device__ unsigned      g_bar_cnt;
__device__ unsigned      g_bar_sense;

// =======================================================================
// conversion / init kernels (rerun each launch; deterministic)
// =======================================================================

__global__ void wconv_kernel(const float* __restrict__ Wi, const float* __restrict__ Wh) {
    __shared__ float s[32][33];
    int l  = blockIdx.z;
    int k0 = blockIdx.x * 32;
    int n0 = blockIdx.y * 32;
    int tx = threadIdx.x, ty = threadIdx.y;

    int k = k0 + ty, n = n0 + tx;
    const float* src = (k < HID)
        ? (Wi + ((size_t)l * HID + k) * GATES + n)
        : (Wh + ((size_t)l * HID + (k - HID)) * GATES + n);
    s[ty][tx] = *src;
    __syncthreads();

    float v  = s[tx][ty];
    int   nn = n0 + ty;
    int   np = 4 * (nn & (HID - 1)) + (nn >> 10);
    __nv_bfloat16 hi = __float2bfloat16(v);
    __nv_bfloat16 lo = __float2bfloat16(v - __bfloat162float(hi));
    g_Whi[l][np][k0 + tx] = hi;
    g_Wlo[l][np][k0 + tx] = lo;
}

__global__ void iconv_kernel(const float* __restrict__ x) {
    size_t i = (size_t)blockIdx.x * blockDim.x + threadIdx.x;
    if (i < (size_t)NSTEP * BATCH * HID) {
        float v = x[i];
        __nv_bfloat16 hi = __float2bfloat16(v);
        __nv_bfloat16 lo = __float2bfloat16(v - __bfloat162float(hi));
        ((__nv_bfloat16*)g_Xhi)[i] = hi;
        ((__nv_bfloat16*)g_Xlo)[i] = lo;
    }
}

__global__ void minit_kernel(const float* __restrict__ b) {
    int i = blockIdx.x * blockDim.x + threadIdx.x;
    if (i < NLAYER * GATES) {
        int l  = i >> 12;
        int n  = i & (GATES - 1);
        int np = 4 * (n & (HID - 1)) + (n >> 10);
        g_bias[l][np] = b[i];
    }
    const int hn = NLAYER * 2 * BATCH * HID;
    for (int j = i; j < hn; j += gridDim.x * blockDim.x) {
        ((__nv_bfloat16*)g_Hhi)[j] = __float2bfloat16(0.f);
        ((__nv_bfloat16*)g_Hlo)[j] = __float2bfloat16(0.f);
    }
    if (i == 0) { g_bar_cnt = 0; g_bar_sense = 0; }
}

// =======================================================================
// persistent LSTM kernel
// =======================================================================

__device__ __forceinline__ void cp16(uint32_t dst, const void* src) {
    asm volatile("cp.async.cg.shared.global [%0], [%1], 16;\n" :: "r"(dst), "l"(src));
}
__device__ __forceinline__ void cp_commit() { asm volatile("cp.async.commit_group;\n"); }
template <int N> __device__ __forceinline__ void cp_wait() {
    asm volatile("cp.async.wait_group %0;\n" :: "n"(N));
}
__device__ __forceinline__ void ldsm4(uint32_t* r, uint32_t addr) {
    asm volatile("ldmatrix.sync.aligned.m8n8.x4.shared.b16 {%0,%1,%2,%3}, [%4];\n"
                 : "=r"(r[0]), "=r"(r[1]), "=r"(r[2]), "=r"(r[3]) : "r"(addr));
}
__device__ __forceinline__ void mma16816(float* c, const uint32_t* a, const uint32_t* b) {
    asm volatile(
        "mma.sync.aligned.m16n8k16.row.col.f32.bf16.bf16.f32 "
        "{%0,%1,%2,%3}, {%4,%5,%6,%7}, {%8,%9}, {%0,%1,%2,%3};\n"
        : "+f"(c[0]), "+f"(c[1]), "+f"(c[2]), "+f"(c[3])
        : "r"(a[0]), "r"(a[1]), "r"(a[2]), "r"(a[3]), "r"(b[0]), "r"(b[1]));
}

__device__ __forceinline__ void grid_sync(unsigned nbar) {
    __threadfence();
    __syncthreads();
    if (threadIdx.x == 0) {
        if (atomicAdd(&g_bar_cnt, 1) == NCTA - 1) {
            g_bar_cnt = 0;
            __threadfence();
            atomicExch(&g_bar_sense, nbar);
        } else {
            while (*(volatile unsigned*)&g_bar_sense < nbar) __nanosleep(64);
            __threadfence();
        }
    }
    __syncthreads();
}

// 3072 x 16B units per KC=128 chunk:
//   A hi/lo: 2 planes * 64 rows * 16 segs = 2048 units
//   W hi/lo: 2 planes * 32 rows * 16 segs = 1024 units
__device__ __forceinline__ void load_chunk(
    uint32_t stg, int kg0,
    const __nv_bfloat16* __restrict__ A1h, const __nv_bfloat16* __restrict__ A1l,
    const __nv_bfloat16* __restrict__ A2h, const __nv_bfloat16* __restrict__ A2l,
    const __nv_bfloat16* __restrict__ Wh_, const __nv_bfloat16* __restrict__ Wl_,
    int tid)
{
    const __nv_bfloat16* Ah; const __nv_bfloat16* Al; int ko;
    if (kg0 < HID) { Ah = A1h; Al = A1l; ko = kg0; }
    else           { Ah = A2h; Al = A2l; ko = kg0 - HID; }
#pragma unroll
    for (int ii = 0; ii < 6; ii++) {
        int u = tid + ii * NTHR;
        if (u < 2048) {
            int plane = u >> 10, v = u & 1023, row = v >> 4, seg = v & 15;
            const __nv_bfloat16* src = (plane ? Al : Ah) + row * HID + ko + seg * 8;
            uint32_t dst = stg + (plane ? ST_ALO : ST_AHI) + (uint32_t)(row * LDA + seg * 8) * 2;
            cp16(dst, src);
        } else {
            int w = u - 2048;
            int plane = w >> 9, v = w & 511, row = v >> 4, seg = v & 15;
            const __nv_bfloat16* src = (plane ? Wl_ : Wh_) + row * KTOT + kg0 + seg * 8;
            uint32_t dst = stg + (plane ? ST_WLO : ST_WHI) + (uint32_t)(row * LDA + seg * 8) * 2;
            cp16(dst, src);
        }
    }
}

__device__ __forceinline__ float sigmoidf_(float x) { return 1.f / (1.f + expf(-x)); }

__global__ void __launch_bounds__(NTHR, 1)
lstm_main(float* __restrict__ out, int out_floats) {
    extern __shared__ char smem[];
    const uint32_t sbase = (uint32_t)__cvta_generic_to_shared(smem);
    const int tid  = threadIdx.x;
    const int bid  = blockIdx.x;
    const int lane = tid & 31, warp = tid >> 5;
    const int ki   = warp & 7;                   // K sub-tile: k16 slice ki within chunk
    const int miB  = warp >> 3;                  // M half: rows [miB*32, miB*32+32)
    const int np0  = bid * NT;

    float* bias_s = (float*)(smem + SM_BIAS);
    for (int i = tid; i < NLAYER * NT; i += NTHR)
        bias_s[i] = g_bias[i >> 5][np0 + (i & 31)];

    float cst[NLAYER];
#pragma unroll
    for (int a = 0; a < NLAYER; a++) cst[a] = 0.f;

    // cell-update mapping: thread owns h element (row_u, hc)
    const int row_u = tid >> 3, hc = tid & 7;
    const int colg  = 8 * bid + hc;

    __syncthreads();
    unsigned nbar = 0;

    for (int t = 0; t < NSTEP; t++) {
        const int par = t & 1, prv = par ^ 1;
        for (int l = 0; l < NLAYER; l++) {
            const __nv_bfloat16* A1h = (l == 0) ? &g_Xhi[t][0][0] : &g_Hhi[l - 1][par][0][0];
            const __nv_bfloat16* A1l = (l == 0) ? &g_Xlo[t][0][0] : &g_Hlo[l - 1][par][0][0];
            const __nv_bfloat16* A2h = &g_Hhi[l][prv][0][0];
            const __nv_bfloat16* A2l = &g_Hlo[l][prv][0][0];
            const __nv_bfloat16* Wh_ = &g_Whi[l][np0][0];
            const __nv_bfloat16* Wl_ = &g_Wlo[l][np0][0];

            float acc[2][4][4];
#pragma unroll
            for (int f = 0; f < 2; f++)
#pragma unroll
                for (int j = 0; j < 4; j++)
#pragma unroll
                    for (int e = 0; e < 4; e++) acc[f][j][e] = 0.f;

            load_chunk(sbase + 0 * ST_BYTES, 0 * KC, A1h, A1l, A2h, A2l, Wh_, Wl_, tid); cp_commit();
            load_chunk(sbase + 1 * ST_BYTES, 1 * KC, A1h, A1l, A2h, A2l, Wh_, Wl_, tid); cp_commit();

            for (int c = 0; c < NCHUNK; c++) {
                if (c < NCHUNK - 1) cp_wait<1>(); else cp_wait<0>();
                __syncthreads();
                if (c + 2 < NCHUNK) {
                    load_chunk(sbase + (uint32_t)((c + 2) % NSTAGE) * ST_BYTES, (c + 2) * KC,
                               A1h, A1l, A2h, A2l, Wh_, Wl_, tid);
                    cp_commit();
                }
                uint32_t stg = sbase + (uint32_t)(c % NSTAGE) * ST_BYTES;

                // A fragments: m32 (2 x m16) x k16 at column ki*16, hi and lo
                uint32_t ah[2][4], al[2][4];
#pragma unroll
                for (int f = 0; f < 2; f++) {
                    uint32_t arow = miB * 32 + f * 16 + (lane & 15);
                    uint32_t acol = ki * 16 + (lane >> 4) * 8;
                    uint32_t aaddr = stg + ST_AHI + (arow * LDA + acol) * 2;
                    ldsm4(ah[f], aaddr);
                    ldsm4(al[f], aaddr + (ST_ALO - ST_AHI));
                }
                // W fragments: n32 (2 x n16) x k16 at column ki*16, hi and lo
                uint32_t bh[2][4], bl[2][4];
#pragma unroll
                for (int g = 0; g < 2; g++) {
                    uint32_t brow = g * 16 + (lane & 7) + ((lane >> 4) & 1) * 8;
                    uint32_t bcol = ki * 16 + ((lane >> 3) & 1) * 8;
                    uint32_t baddr = stg + ST_WHI + (brow * LDA + bcol) * 2;
                    ldsm4(bh[g], baddr);
                    ldsm4(bl[g], baddr + (ST_WLO - ST_WHI));
                }
#pragma unroll
                for (int f = 0; f < 2; f++)
#pragma unroll
                    for (int j = 0; j < 4; j++) {
                        uint32_t* bhp = &bh[j >> 1][(j & 1) * 2];
                        uint32_t* blp = &bl[j >> 1][(j & 1) * 2];
                        mma16816(acc[f][j], ah[f], bhp);
                        mma16816(acc[f][j], ah[f], blp);
                        mma16816(acc[f][j], al[f], bhp);
                    }
            }

            // dump partial gates to buffer ki (stages 1-2 region; all stages drained)
            {
                float* gs = (float*)(smem + SM_GATES + ki * 9216);
#pragma unroll
                for (int f = 0; f < 2; f++) {
                    int r0 = miB * 32 + f * 16 + (lane >> 2);
#pragma unroll
                    for (int j = 0; j < 4; j++) {
                        int c0 = j * 8 + (lane & 3) * 2;
                        *(float2*)&gs[(r0    ) * LDC + c0] = make_float2(acc[f][j][0], acc[f][j][1]);
                        *(float2*)&gs[(r0 + 8) * LDC + c0] = make_float2(acc[f][j][2], acc[f][j][3]);
                    }
                }
            }
            __syncthreads();

            // cell update: sum the 8 K-partials + bias
            {
                float4 bb = *(const float4*)&bias_s[l * NT + 4 * hc];
                float i0 = bb.x, f0 = bb.y, gg = bb.z, o0 = bb.w;
#pragma unroll
                for (int kb = 0; kb < 8; kb++) {
                    const float* g = (const float*)(smem + SM_GATES + kb * 9216);
                    float4 p = *(const float4*)&g[row_u * LDC + 4 * hc];
                    i0 += p.x; f0 += p.y; gg += p.z; o0 += p.w;
                }

                float cn = sigmoidf_(f0) * cst[l] + sigmoidf_(i0) * tanhf(gg);
                cst[l] = cn;
                float h = sigmoidf_(o0) * tanhf(cn);

                __nv_bfloat16 hh = __float2bfloat16(h);
                __nv_bfloat16 hl = __float2bfloat16(h - __bfloat162float(hh));
                g_Hhi[l][par][row_u][colg] = hh;
                g_Hlo[l][par][row_u][colg] = hl;

                if (l == NLAYER - 1 && t == NSTEP - 1) {
                    int idx = row_u * HID + colg;
                    out[idx] = h;                                           // output
                    if (out_floats >= 2 * BH) out[BH + idx] = h;            // h final
                    if (out_floats >= 3 * BH) out[2 * BH + idx] = cn;       // c final
                }
            }

            nbar++;
            grid_sync(nbar);
        }
    }
}

// =======================================================================
// launch
// =======================================================================
extern "C" void kernel_launch(void* const* d_in, const int* in_sizes, int n_in,
                              void* d_out, int out_size) {
    const float* x  = (const float*)d_in[0];
    const float* Wi = (const float*)d_in[1];
    const float* Wh = (const float*)d_in[2];
    const float* b  = (const float*)d_in[3];
    float* out = (float*)d_out;

    cudaFuncSetAttribute(lstm_main, cudaFuncAttributeMaxDynamicSharedMemorySize, SM_TOTAL);

    minit_kernel<<<64, 256>>>(b);
    wconv_kernel<<<dim3(KTOT / 32, GATES / 32, NLAYER), dim3(32, 32)>>>(Wi, Wh);
    iconv_kernel<<<(NSTEP * BATCH * HID + 255) / 256, 256>>>(x);
    lstm_main<<<NCTA, NTHR, SM_TOTAL>>>(out, out_size);
}

// round 13
// speedup vs baseline: 1.3936x; 1.0060x over previous
#include <cuda_runtime.h>
#include <cuda_bf16.h>
#include <cstdint>
#include <math.h>

// ---------------- problem constants ----------------
#define NLAYER 4
#define HID    1024
#define BATCH  64
#define NSTEP  128
#define GATES  4096            // 4*HID
#define KTOT   2048            // x-part (1024) + h-part (1024)
#define BH     (BATCH * HID)
#define NSTEPS_TOT (NSTEP * NLAYER)

// ---------------- kernel config --------------------
#define NCTA   128             // 1 CTA per SM, co-resident -> grid barrier safe
#define NTHR   512             // 16 warps: 2 (M-split, m32) x 8 (K-split, k16 each)
#define NT     32              // permuted gate columns per CTA (8 h-cols x 4 gates)
#define KC     128             // K per pipeline chunk
#define NCHUNK (KTOT / KC)     // 16
#define NSTAGE 3
#define LDA    136             // padded smem row stride (bf16) -> conflict-free ldsm
#define LDC    36              // gates smem row stride (floats)

// smem stage layout (bytes)
#define ST_AHI   0
#define ST_ALO   17408         // 64*136*2
#define ST_WHI   34816
#define ST_WLO   43520         // + 32*136*2
#define ST_BYTES 52224
// 8 gate partial buffers (64 x 36 floats = 9216 B each) live in stages 1..2.
// Prefetch of next-step chunks 0,1 (stages 0,1) happens only AFTER the
// post-cell-update __syncthreads, which fences all gate reads.
#define SM_GATES ST_BYTES                          // [52224, 125952) in stages 1-2
#define SM_BIAS  (NSTAGE * ST_BYTES)               // 156672
#define SM_TOTAL (SM_BIAS + NLAYER * NT * 4)       // 157184

// ---------------- device scratch (allocation-free rule) ----------------
__device__ __nv_bfloat16 g_Whi[NLAYER][GATES][KTOT];   // [l][np][k], k contiguous
__device__ __nv_bfloat16 g_Wlo[NLAYER][GATES][KTOT];
__device__ __nv_bfloat16 g_Xhi[NSTEP][BATCH][HID];
__device__ __nv_bfloat16 g_Xlo[NSTEP][BATCH][HID];
__device__ __nv_bfloat16 g_Hhi[NLAYER][2][BATCH][HID]; // ping-pong on step parity
__device__ __nv_bfloat16 g_Hlo[NLAYER][2][BATCH][HID];
__device__ float         g_bias[NLAYER][GATES];        // permuted
__device__ unsigned      g_bar_cnt;
__device__ unsigned      g_bar_sense;

// =======================================================================
// conversion / init kernels (rerun each launch; deterministic)
// =======================================================================

__global__ void wconv_kernel(const float* __restrict__ Wi, const float* __restrict__ Wh) {
    __shared__ float s[32][33];
    int l  = blockIdx.z;
    int k0 = blockIdx.x * 32;
    int n0 = blockIdx.y * 32;
    int tx = threadIdx.x, ty = threadIdx.y;

    int k = k0 + ty, n = n0 + tx;
    const float* src = (k < HID)
        ? (Wi + ((size_t)l * HID + k) * GATES + n)
        : (Wh + ((size_t)l * HID + (k - HID)) * GATES + n);
    s[ty][tx] = *src;
    __syncthreads();

    float v  = s[tx][ty];
    int   nn = n0 + ty;
    int   np = 4 * (nn & (HID - 1)) + (nn >> 10);
    __nv_bfloat16 hi = __float2bfloat16(v);
    __nv_bfloat16 lo = __float2bfloat16(v - __bfloat162float(hi));
    g_Whi[l][np][k0 + tx] = hi;
    g_Wlo[l][np][k0 + tx] = lo;
}

__global__ void iconv_kernel(const float* __restrict__ x) {
    size_t i = (size_t)blockIdx.x * blockDim.x + threadIdx.x;
    if (i < (size_t)NSTEP * BATCH * HID) {
        float v = x[i];
        __nv_bfloat16 hi = __float2bfloat16(v);
        __nv_bfloat16 lo = __float2bfloat16(v - __bfloat162float(hi));
        ((__nv_bfloat16*)g_Xhi)[i] = hi;
        ((__nv_bfloat16*)g_Xlo)[i] = lo;
    }
}

__global__ void minit_kernel(const float* __restrict__ b) {
    int i = blockIdx.x * blockDim.x + threadIdx.x;
    if (i < NLAYER * GATES) {
        int l  = i >> 12;
        int n  = i & (GATES - 1);
        int np = 4 * (n & (HID - 1)) + (n >> 10);
        g_bias[l][np] = b[i];
    }
    const int hn = NLAYER * 2 * BATCH * HID;
    for (int j = i; j < hn; j += gridDim.x * blockDim.x) {
        ((__nv_bfloat16*)g_Hhi)[j] = __float2bfloat16(0.f);
        ((__nv_bfloat16*)g_Hlo)[j] = __float2bfloat16(0.f);
    }
    if (i == 0) { g_bar_cnt = 0; g_bar_sense = 0; }
}

// =======================================================================
// persistent LSTM kernel
// =======================================================================

__device__ __forceinline__ void cp16(uint32_t dst, const void* src) {
    asm volatile("cp.async.cg.shared.global [%0], [%1], 16;\n" :: "r"(dst), "l"(src));
}
__device__ __forceinline__ void cp_commit() { asm volatile("cp.async.commit_group;\n"); }
template <int N> __device__ __forceinline__ void cp_wait() {
    asm volatile("cp.async.wait_group %0;\n" :: "n"(N));
}
__device__ __forceinline__ void ldsm4(uint32_t* r, uint32_t addr) {
    asm volatile("ldmatrix.sync.aligned.m8n8.x4.shared.b16 {%0,%1,%2,%3}, [%4];\n"
                 : "=r"(r[0]), "=r"(r[1]), "=r"(r[2]), "=r"(r[3]) : "r"(addr));
}
__device__ __forceinline__ void mma16816(float* c, const uint32_t* a, const uint32_t* b) {
    asm volatile(
        "mma.sync.aligned.m16n8k16.row.col.f32.bf16.bf16.f32 "
        "{%0,%1,%2,%3}, {%4,%5,%6,%7}, {%8,%9}, {%0,%1,%2,%3};\n"
        : "+f"(c[0]), "+f"(c[1]), "+f"(c[2]), "+f"(c[3])
        : "r"(a[0]), "r"(a[1]), "r"(a[2]), "r"(a[3]), "r"(b[0]), "r"(b[1]));
}

__device__ __forceinline__ void grid_sync(unsigned nbar) {
    __threadfence();
    __syncthreads();
    if (threadIdx.x == 0) {
        if (atomicAdd(&g_bar_cnt, 1) == NCTA - 1) {
            g_bar_cnt = 0;
            __threadfence();
            atomicExch(&g_bar_sense, nbar);
        } else {
            while (*(volatile unsigned*)&g_bar_sense < nbar) __nanosleep(64);
            __threadfence();
        }
    }
    __syncthreads();
}

// chunk order: c=0..7 -> h-part (kg0 >= HID, barrier-independent),
//              c=8..15 -> x-part (depends on h of layer l-1 / X)
__device__ __forceinline__ int chunk_kg0(int c) {
    return (c < 8) ? (HID + c * KC) : ((c - 8) * KC);
}

// 3072 x 16B units per KC=128 chunk:
//   A hi/lo: 2 planes * 64 rows * 16 segs = 2048 units
//   W hi/lo: 2 planes * 32 rows * 16 segs = 1024 units
__device__ __forceinline__ void load_chunk(
    uint32_t stg, int kg0,
    const __nv_bfloat16* __restrict__ A1h, const __nv_bfloat16* __restrict__ A1l,
    const __nv_bfloat16* __restrict__ A2h, const __nv_bfloat16* __restrict__ A2l,
    const __nv_bfloat16* __restrict__ Wh_, const __nv_bfloat16* __restrict__ Wl_,
    int tid)
{
    const __nv_bfloat16* Ah; const __nv_bfloat16* Al; int ko;
    if (kg0 < HID) { Ah = A1h; Al = A1l; ko = kg0; }
    else           { Ah = A2h; Al = A2l; ko = kg0 - HID; }
#pragma unroll
    for (int ii = 0; ii < 6; ii++) {
        int u = tid + ii * NTHR;
        if (u < 2048) {
            int plane = u >> 10, v = u & 1023, row = v >> 4, seg = v & 15;
            const __nv_bfloat16* src = (plane ? Al : Ah) + row * HID + ko + seg * 8;
            uint32_t dst = stg + (plane ? ST_ALO : ST_AHI) + (uint32_t)(row * LDA + seg * 8) * 2;
            cp16(dst, src);
        } else {
            int w = u - 2048;
            int plane = w >> 9, v = w & 511, row = v >> 4, seg = v & 15;
            const __nv_bfloat16* src = (plane ? Wl_ : Wh_) + row * KTOT + kg0 + seg * 8;
            uint32_t dst = stg + (plane ? ST_WLO : ST_WHI) + (uint32_t)(row * LDA + seg * 8) * 2;
            cp16(dst, src);
        }
    }
}

__device__ __forceinline__ float sigmoidf_(float x) { return 1.f / (1.f + expf(-x)); }

__global__ void __launch_bounds__(NTHR, 1)
lstm_main(float* __restrict__ out, int out_floats) {
    extern __shared__ char smem[];
    const uint32_t sbase = (uint32_t)__cvta_generic_to_shared(smem);
    const int tid  = threadIdx.x;
    const int bid  = blockIdx.x;
    const int lane = tid & 31, warp = tid >> 5;
    const int ki   = warp & 7;                   // K sub-tile: k16 slice ki within chunk
    const int miB  = warp >> 3;                  // M half: rows [miB*32, miB*32+32)
    const int np0  = bid * NT;

    float* bias_s = (float*)(smem + SM_BIAS);
    for (int i = tid; i < NLAYER * NT; i += NTHR)
        bias_s[i] = g_bias[i >> 5][np0 + (i & 31)];

    float cst[NLAYER];
#pragma unroll
    for (int a = 0; a < NLAYER; a++) cst[a] = 0.f;

    // cell-update mapping: thread owns h element (row_u, hc)
    const int row_u = tid >> 3, hc = tid & 7;
    const int colg  = 8 * bid + hc;

    __syncthreads();
    unsigned nbar = 0;

    // prefetch chunks 0,1 (h-part) of the first layer-step
    {
        const __nv_bfloat16* A2h = &g_Hhi[0][1][0][0];
        const __nv_bfloat16* A2l = &g_Hlo[0][1][0][0];
        const __nv_bfloat16* Wh_ = &g_Whi[0][np0][0];
        const __nv_bfloat16* Wl_ = &g_Wlo[0][np0][0];
        load_chunk(sbase + 0 * ST_BYTES, chunk_kg0(0), 0, 0, A2h, A2l, Wh_, Wl_, tid); cp_commit();
        load_chunk(sbase + 1 * ST_BYTES, chunk_kg0(1), 0, 0, A2h, A2l, Wh_, Wl_, tid); cp_commit();
    }

    for (int s = 0; s < NSTEPS_TOT; s++) {
        const int t = s >> 2, l = s & 3;
        const int par = t & 1, prv = par ^ 1;
        const __nv_bfloat16* A1h = (l == 0) ? &g_Xhi[t][0][0] : &g_Hhi[l - 1][par][0][0];
        const __nv_bfloat16* A1l = (l == 0) ? &g_Xlo[t][0][0] : &g_Hlo[l - 1][par][0][0];
        const __nv_bfloat16* A2h = &g_Hhi[l][prv][0][0];
        const __nv_bfloat16* A2l = &g_Hlo[l][prv][0][0];
        const __nv_bfloat16* Wh_ = &g_Whi[l][np0][0];
        const __nv_bfloat16* Wl_ = &g_Wlo[l][np0][0];

        float acc[2][4][4];
#pragma unroll
        for (int f = 0; f < 2; f++)
#pragma unroll
            for (int j = 0; j < 4; j++)
#pragma unroll
                for (int e = 0; e < 4; e++) acc[f][j][e] = 0.f;

        for (int c = 0; c < NCHUNK; c++) {
            if (c < NCHUNK - 1) cp_wait<1>(); else cp_wait<0>();
            __syncthreads();
            if (c + 2 < NCHUNK) {
                load_chunk(sbase + (uint32_t)((c + 2) % NSTAGE) * ST_BYTES, chunk_kg0(c + 2),
                           A1h, A1l, A2h, A2l, Wh_, Wl_, tid);
                cp_commit();
            }
            uint32_t stg = sbase + (uint32_t)(c % NSTAGE) * ST_BYTES;

            // A fragments: m32 (2 x m16) x k16 at column ki*16, hi and lo
            uint32_t ah[2][4], al[2][4];
#pragma unroll
            for (int f = 0; f < 2; f++) {
                uint32_t arow = miB * 32 + f * 16 + (lane & 15);
                uint32_t acol = ki * 16 + (lane >> 4) * 8;
                uint32_t aaddr = stg + ST_AHI + (arow * LDA + acol) * 2;
                ldsm4(ah[f], aaddr);
                ldsm4(al[f], aaddr + (ST_ALO - ST_AHI));
            }
            // W fragments: n32 (2 x n16) x k16 at column ki*16, hi and lo
            uint32_t bh[2][4], bl[2][4];
#pragma unroll
            for (int g = 0; g < 2; g++) {
                uint32_t brow = g * 16 + (lane & 7) + ((lane >> 4) & 1) * 8;
                uint32_t bcol = ki * 16 + ((lane >> 3) & 1) * 8;
                uint32_t baddr = stg + ST_WHI + (brow * LDA + bcol) * 2;
                ldsm4(bh[g], baddr);
                ldsm4(bl[g], baddr + (ST_WLO - ST_WHI));
            }
#pragma unroll
            for (int f = 0; f < 2; f++)
#pragma unroll
                for (int j = 0; j < 4; j++) {
                    uint32_t* bhp = &bh[j >> 1][(j & 1) * 2];
                    uint32_t* blp = &bl[j >> 1][(j & 1) * 2];
                    mma16816(acc[f][j], ah[f], bhp);
                    mma16816(acc[f][j], ah[f], blp);
                    mma16816(acc[f][j], al[f], bhp);
                }
        }

        // dump partial gates to buffer ki (stages 1-2 region; all stages drained)
        {
            float* gs = (float*)(smem + SM_GATES + ki * 9216);
#pragma unroll
            for (int f = 0; f < 2; f++) {
                int r0 = miB * 32 + f * 16 + (lane >> 2);
#pragma unroll
                for (int j = 0; j < 4; j++) {
                    int c0 = j * 8 + (lane & 3) * 2;
                    *(float2*)&gs[(r0    ) * LDC + c0] = make_float2(acc[f][j][0], acc[f][j][1]);
                    *(float2*)&gs[(r0 + 8) * LDC + c0] = make_float2(acc[f][j][2], acc[f][j][3]);
                }
            }
        }
        __syncthreads();

        // cell update: sum the 8 K-partials + bias
        {
            float4 bb = *(const float4*)&bias_s[l * NT + 4 * hc];
            float i0 = bb.x, f0 = bb.y, gg = bb.z, o0 = bb.w;
#pragma unroll
            for (int kb = 0; kb < 8; kb++) {
                const float* g = (const float*)(smem + SM_GATES + kb * 9216);
                float4 p = *(const float4*)&g[row_u * LDC + 4 * hc];
                i0 += p.x; f0 += p.y; gg += p.z; o0 += p.w;
            }

            float cn = sigmoidf_(f0) * cst[l] + sigmoidf_(i0) * tanhf(gg);
            cst[l] = cn;
            float h = sigmoidf_(o0) * tanhf(cn);

            __nv_bfloat16 hh = __float2bfloat16(h);
            __nv_bfloat16 hl = __float2bfloat16(h - __bfloat162float(hh));
            g_Hhi[l][par][row_u][colg] = hh;
            g_Hlo[l][par][row_u][colg] = hl;

            if (s == NSTEPS_TOT - 1) {
                int idx = row_u * HID + colg;
                out[idx] = h;                                           // output
                if (out_floats >= 2 * BH) out[BH + idx] = h;            // h final
                if (out_floats >= 3 * BH) out[2 * BH + idx] = cn;       // c final
            }
        }

        __syncthreads();   // fence gate reads before prefetch overwrites stage 1

        // prefetch next layer-step's chunks 0,1 (h-part: only A2'/W' are read,
        // both stable since >=3 barriers ago) -> loads fly during the barrier
        if (s + 1 < NSTEPS_TOT) {
            const int t2 = (s + 1) >> 2, l2 = (s + 1) & 3;
            const int prv2 = (t2 & 1) ^ 1;
            const __nv_bfloat16* nA2h = &g_Hhi[l2][prv2][0][0];
            const __nv_bfloat16* nA2l = &g_Hlo[l2][prv2][0][0];
            const __nv_bfloat16* nWh  = &g_Whi[l2][np0][0];
            const __nv_bfloat16* nWl  = &g_Wlo[l2][np0][0];
            load_chunk(sbase + 0 * ST_BYTES, chunk_kg0(0), 0, 0, nA2h, nA2l, nWh, nWl, tid); cp_commit();
            load_chunk(sbase + 1 * ST_BYTES, chunk_kg0(1), 0, 0, nA2h, nA2l, nWh, nWl, tid); cp_commit();
        }

        nbar++;
        grid_sync(nbar);
    }
}

// =======================================================================
// launch
// =======================================================================
extern "C" void kernel_launch(void* const* d_in, const int* in_sizes, int n_in,
                              void* d_out, int out_size) {
    const float* x  = (const float*)d_in[0];
    const float* Wi = (const float*)d_in[1];
    const float* Wh = (const float*)d_in[2];
    const float* b  = (const float*)d_in[3];
    float* out = (float*)d_out;

    cudaFuncSetAttribute(lstm_main, cudaFuncAttributeMaxDynamicSharedMemorySize, SM_TOTAL);

    minit_kernel<<<64, 256>>>(b);
    wconv_kernel<<<dim3(KTOT / 32, GATES / 32, NLAYER), dim3(32, 32)>>>(Wi, Wh);
    iconv_kernel<<<(NSTEP * BATCH * HID + 255) / 256, 256>>>(x);
    lstm_main<<<NCTA, NTHR, SM_TOTAL>>>(out, out_size);
}

// round 14
// speedup vs baseline: 1.9153x; 1.3744x over previous
#include <cuda_runtime.h>
#include <cuda_bf16.h>
#include <cstdint>
#include <math.h>

// ---------------- problem constants ----------------
#define NLAYER 4
#define HID    1024
#define BATCH  64
#define NSTEP  128
#define GATES  4096            // 4*HID
#define KTOT   2048            // x-part (1024) + h-part (1024)
#define BH     (BATCH * HID)
#define NDIAG  (NSTEP + NLAYER - 1)   // 131 wavefront diagonals

// ---------------- kernel config --------------------
#define NCTA   128             // 4 layers x 32 col-blocks; 1 CTA/SM -> barrier safe
#define NTHR   512             // 16 warps: 2(M,m32) x 4(N,n32) x 2(K-split)
#define NT     128             // permuted gate columns per CTA (32 h-cols x 4 gates)
#define KC     128             // K per pipeline chunk
#define NCHUNK (KTOT / KC)     // 16
#define LDA    136             // padded smem row stride (bf16) -> conflict-free ldsm
#define LDC    132             // gates smem row stride (floats)

// smem stage layout (bytes)
#define ST_AHI   0
#define ST_ALO   17408         // 64*136*2
#define ST_WHI   34816
#define ST_WLO   69632         // + 128*136*2
#define ST_BYTES 104448        // A(2 planes) + W(2 planes)
// 2 gate partial buffers (64 x 132 floats = 33792 B each) overlap stage 0.
#define SM_GS0   0
#define SM_GS1   33792
#define SM_BIAS  (2 * ST_BYTES)            // 208896
#define SM_TOTAL (SM_BIAS + NT * 4)        // 209408

// ---------------- device scratch (allocation-free rule) ----------------
__device__ __nv_bfloat16 g_Whi[NLAYER][GATES][KTOT];   // [l][np][k], k contiguous
__device__ __nv_bfloat16 g_Wlo[NLAYER][GATES][KTOT];
__device__ __nv_bfloat16 g_Xhi[NSTEP][BATCH][HID];
__device__ __nv_bfloat16 g_Xlo[NSTEP][BATCH][HID];
__device__ __nv_bfloat16 g_Hhi[NLAYER][2][BATCH][HID]; // ping-pong on step parity
__device__ __nv_bfloat16 g_Hlo[NLAYER][2][BATCH][HID];
__device__ float         g_bias[NLAYER][GATES];        // permuted
__device__ unsigned      g_bar_cnt;
__device__ unsigned      g_bar_sense;

// =======================================================================
// conversion / init kernels (rerun each launch; deterministic)
// =======================================================================

__global__ void wconv_kernel(const float* __restrict__ Wi, const float* __restrict__ Wh) {
    __shared__ float s[32][33];
    int l  = blockIdx.z;
    int k0 = blockIdx.x * 32;
    int n0 = blockIdx.y * 32;
    int tx = threadIdx.x, ty = threadIdx.y;

    int k = k0 + ty, n = n0 + tx;
    const float* src = (k < HID)
        ? (Wi + ((size_t)l * HID + k) * GATES + n)
        : (Wh + ((size_t)l * HID + (k - HID)) * GATES + n);
    s[ty][tx] = *src;
    __syncthreads();

    float v  = s[tx][ty];
    int   nn = n0 + ty;
    int   np = 4 * (nn & (HID - 1)) + (nn >> 10);
    __nv_bfloat16 hi = __float2bfloat16(v);
    __nv_bfloat16 lo = __float2bfloat16(v - __bfloat162float(hi));
    g_Whi[l][np][k0 + tx] = hi;
    g_Wlo[l][np][k0 + tx] = lo;
}

__global__ void iconv_kernel(const float* __restrict__ x) {
    size_t i = (size_t)blockIdx.x * blockDim.x + threadIdx.x;
    if (i < (size_t)NSTEP * BATCH * HID) {
        float v = x[i];
        __nv_bfloat16 hi = __float2bfloat16(v);
        __nv_bfloat16 lo = __float2bfloat16(v - __bfloat162float(hi));
        ((__nv_bfloat16*)g_Xhi)[i] = hi;
        ((__nv_bfloat16*)g_Xlo)[i] = lo;
    }
}

__global__ void minit_kernel(const float* __restrict__ b) {
    int i = blockIdx.x * blockDim.x + threadIdx.x;
    if (i < NLAYER * GATES) {
        int l  = i >> 12;
        int n  = i & (GATES - 1);
        int np = 4 * (n & (HID - 1)) + (n >> 10);
        g_bias[l][np] = b[i];
    }
    const int hn = NLAYER * 2 * BATCH * HID;
    for (int j = i; j < hn; j += gridDim.x * blockDim.x) {
        ((__nv_bfloat16*)g_Hhi)[j] = __float2bfloat16(0.f);
        ((__nv_bfloat16*)g_Hlo)[j] = __float2bfloat16(0.f);
    }
    if (i == 0) { g_bar_cnt = 0; g_bar_sense = 0; }
}

// =======================================================================
// persistent LSTM kernel (layer wavefront)
// =======================================================================

__device__ __forceinline__ void cp16(uint32_t dst, const void* src) {
    asm volatile("cp.async.cg.shared.global [%0], [%1], 16;\n" :: "r"(dst), "l"(src));
}
__device__ __forceinline__ void cp_commit() { asm volatile("cp.async.commit_group;\n"); }
template <int N> __device__ __forceinline__ void cp_wait() {
    asm volatile("cp.async.wait_group %0;\n" :: "n"(N));
}
__device__ __forceinline__ void ldsm4(uint32_t* r, uint32_t addr) {
    asm volatile("ldmatrix.sync.aligned.m8n8.x4.shared.b16 {%0,%1,%2,%3}, [%4];\n"
                 : "=r"(r[0]), "=r"(r[1]), "=r"(r[2]), "=r"(r[3]) : "r"(addr));
}
__device__ __forceinline__ void mma16816(float* c, const uint32_t* a, const uint32_t* b) {
    asm volatile(
        "mma.sync.aligned.m16n8k16.row.col.f32.bf16.bf16.f32 "
        "{%0,%1,%2,%3}, {%4,%5,%6,%7}, {%8,%9}, {%0,%1,%2,%3};\n"
        : "+f"(c[0]), "+f"(c[1]), "+f"(c[2]), "+f"(c[3])
        : "r"(a[0]), "r"(a[1]), "r"(a[2]), "r"(a[3]), "r"(b[0]), "r"(b[1]));
}

__device__ __forceinline__ void grid_sync(unsigned nbar) {
    __threadfence();
    __syncthreads();
    if (threadIdx.x == 0) {
        if (atomicAdd(&g_bar_cnt, 1) == NCTA - 1) {
            g_bar_cnt = 0;
            __threadfence();
            atomicExch(&g_bar_sense, nbar);
        } else {
            while (*(volatile unsigned*)&g_bar_sense < nbar) __nanosleep(64);
            __threadfence();
        }
    }
    __syncthreads();
}

// 6144 x 16B units per KC=128 chunk:
//   A hi/lo: 2 planes * 64 rows * 16 segs  = 2048 units
//   W hi/lo: 2 planes * 128 rows * 16 segs = 4096 units
__device__ __forceinline__ void load_chunk(
    uint32_t stg, int kg0,
    const __nv_bfloat16* __restrict__ A1h, const __nv_bfloat16* __restrict__ A1l,
    const __nv_bfloat16* __restrict__ A2h, const __nv_bfloat16* __restrict__ A2l,
    const __nv_bfloat16* __restrict__ Wh_, const __nv_bfloat16* __restrict__ Wl_,
    int tid)
{
    const __nv_bfloat16* Ah; const __nv_bfloat16* Al; int ko;
    if (kg0 < HID) { Ah = A1h; Al = A1l; ko = kg0; }
    else           { Ah = A2h; Al = A2l; ko = kg0 - HID; }
#pragma unroll
    for (int ii = 0; ii < 12; ii++) {
        int u = tid + ii * NTHR;
        if (u < 2048) {
            int plane = u >> 10, v = u & 1023, row = v >> 4, seg = v & 15;
            const __nv_bfloat16* src = (plane ? Al : Ah) + row * HID + ko + seg * 8;
            uint32_t dst = stg + (plane ? ST_ALO : ST_AHI) + (uint32_t)(row * LDA + seg * 8) * 2;
            cp16(dst, src);
        } else {
            int w = u - 2048;
            int plane = w >> 11, v = w & 2047, row = v >> 4, seg = v & 15;
            const __nv_bfloat16* src = (plane ? Wl_ : Wh_) + row * KTOT + kg0 + seg * 8;
            uint32_t dst = stg + (plane ? ST_WLO : ST_WHI) + (uint32_t)(row * LDA + seg * 8) * 2;
            cp16(dst, src);
        }
    }
}

__device__ __forceinline__ float sigmoidf_(float x) { return 1.f / (1.f + expf(-x)); }

__global__ void __launch_bounds__(NTHR, 1)
lstm_main(float* __restrict__ out, int out_floats) {
    extern __shared__ char smem[];
    const uint32_t sbase = (uint32_t)__cvta_generic_to_shared(smem);
    const int tid  = threadIdx.x;
    const int bid  = blockIdx.x;
    const int lane = tid & 31, warp = tid >> 5;
    const int kiB  = warp & 1;                 // K half (8 k16-slices -> 4 each)
    const int njB  = (warp >> 1) & 3;          // N tile: cols [njB*32, njB*32+32)
    const int miB  = warp >> 3;                // M half: rows [miB*32, miB*32+32)

    const int l_own = bid >> 5;                // this CTA's layer
    const int cb    = bid & 31;                // column block
    const int np0   = cb * NT;                 // gate cols [np0, np0+128)

    float* bias_s = (float*)(smem + SM_BIAS);
    for (int i = tid; i < NT; i += NTHR)
        bias_s[i] = g_bias[l_own][np0 + i];

    // cell-update mapping: thread owns rows row_u, 4 local h-cols hb..hb+3
    const int row_u = tid >> 3, hb = (tid & 7) * 4;
    float cst[4];
#pragma unroll
    for (int e = 0; e < 4; e++) cst[e] = 0.f;

    const __nv_bfloat16* Wh_ = &g_Whi[l_own][np0][0];
    const __nv_bfloat16* Wl_ = &g_Wlo[l_own][np0][0];

    __syncthreads();
    unsigned nbar = 0;

    for (int d = 0; d < NDIAG; d++) {
        const int t = d - l_own;
        if (t >= 0 && t < NSTEP) {
            const int par = t & 1, prv = par ^ 1;
            const __nv_bfloat16* A1h = (l_own == 0) ? &g_Xhi[t][0][0] : &g_Hhi[l_own - 1][par][0][0];
            const __nv_bfloat16* A1l = (l_own == 0) ? &g_Xlo[t][0][0] : &g_Hlo[l_own - 1][par][0][0];
            const __nv_bfloat16* A2h = &g_Hhi[l_own][prv][0][0];
            const __nv_bfloat16* A2l = &g_Hlo[l_own][prv][0][0];

            float acc[2][4][4];
#pragma unroll
            for (int f = 0; f < 2; f++)
#pragma unroll
                for (int j = 0; j < 4; j++)
#pragma unroll
                    for (int e = 0; e < 4; e++) acc[f][j][e] = 0.f;

            load_chunk(sbase, 0, A1h, A1l, A2h, A2l, Wh_, Wl_, tid); cp_commit();

            for (int c = 0; c < NCHUNK; c++) {
                cp_wait<0>();
                __syncthreads();
                if (c + 1 < NCHUNK) {
                    load_chunk(sbase + (uint32_t)((c + 1) & 1) * ST_BYTES, (c + 1) * KC,
                               A1h, A1l, A2h, A2l, Wh_, Wl_, tid);
                    cp_commit();
                }
                uint32_t stg = sbase + (uint32_t)(c & 1) * ST_BYTES;

#pragma unroll
                for (int q = 0; q < 4; q++) {
                    int ks = kiB * 4 + q;
                    // A fragments: m32 (2 x m16) x k16 at column ks*16, hi and lo
                    uint32_t ah[2][4], al[2][4];
#pragma unroll
                    for (int f = 0; f < 2; f++) {
                        uint32_t arow = miB * 32 + f * 16 + (lane & 15);
                        uint32_t acol = ks * 16 + (lane >> 4) * 8;
                        uint32_t aaddr = stg + ST_AHI + (arow * LDA + acol) * 2;
                        ldsm4(ah[f], aaddr);
                        ldsm4(al[f], aaddr + (ST_ALO - ST_AHI));
                    }
                    // W fragments: n32 (2 x n16) x k16, hi and lo
                    uint32_t bh[2][4], bl[2][4];
#pragma unroll
                    for (int g = 0; g < 2; g++) {
                        uint32_t brow = njB * 32 + g * 16 + (lane & 7) + ((lane >> 4) & 1) * 8;
                        uint32_t bcol = ks * 16 + ((lane >> 3) & 1) * 8;
                        uint32_t baddr = stg + ST_WHI + (brow * LDA + bcol) * 2;
                        ldsm4(bh[g], baddr);
                        ldsm4(bl[g], baddr + (ST_WLO - ST_WHI));
                    }
#pragma unroll
                    for (int f = 0; f < 2; f++)
#pragma unroll
                        for (int j = 0; j < 4; j++) {
                            uint32_t* bhp = &bh[j >> 1][(j & 1) * 2];
                            uint32_t* blp = &bl[j >> 1][(j & 1) * 2];
                            mma16816(acc[f][j], ah[f], bhp);
                            mma16816(acc[f][j], ah[f], blp);
                            mma16816(acc[f][j], al[f], bhp);
                        }
                }
            }

            // dump partial gates to buffer kiB (overlaps stage 0; all reads fenced)
            {
                float* gs = (float*)(smem + (kiB ? SM_GS1 : SM_GS0));
#pragma unroll
                for (int f = 0; f < 2; f++) {
                    int r0 = miB * 32 + f * 16 + (lane >> 2);
#pragma unroll
                    for (int j = 0; j < 4; j++) {
                        int c0 = njB * 32 + j * 8 + (lane & 3) * 2;
                        *(float2*)&gs[(r0    ) * LDC + c0] = make_float2(acc[f][j][0], acc[f][j][1]);
                        *(float2*)&gs[(r0 + 8) * LDC + c0] = make_float2(acc[f][j][2], acc[f][j][3]);
                    }
                }
            }
            __syncthreads();

            // cell update: 4 h-elements per thread; sum 2 K-partials + bias
            {
                const float* g0 = (const float*)(smem + SM_GS0);
                const float* g1 = (const float*)(smem + SM_GS1);
#pragma unroll
                for (int e = 0; e < 4; e++) {
                    int hl = hb + e;
                    float4 p0 = *(const float4*)&g0[row_u * LDC + 4 * hl];
                    float4 p1 = *(const float4*)&g1[row_u * LDC + 4 * hl];
                    float4 bb = *(const float4*)&bias_s[4 * hl];

                    float i0 = p0.x + p1.x + bb.x;
                    float f0 = p0.y + p1.y + bb.y;
                    float gg = p0.z + p1.z + bb.z;
                    float o0 = p0.w + p1.w + bb.w;

                    float cn = sigmoidf_(f0) * cst[e] + sigmoidf_(i0) * tanhf(gg);
                    cst[e] = cn;
                    float h = sigmoidf_(o0) * tanhf(cn);

                    int colg = cb * 32 + hl;
                    __nv_bfloat16 hh = __float2bfloat16(h);
                    __nv_bfloat16 hl16 = __float2bfloat16(h - __bfloat162float(hh));
                    g_Hhi[l_own][par][row_u][colg] = hh;
                    g_Hlo[l_own][par][row_u][colg] = hl16;

                    if (l_own == NLAYER - 1 && t == NSTEP - 1) {
                        int idx = row_u * HID + colg;
                        out[idx] = h;                                       // output
                        if (out_floats >= 2 * BH) out[BH + idx] = h;        // h final
                        if (out_floats >= 3 * BH) out[2 * BH + idx] = cn;   // c final
                    }
                }
            }
        }

        nbar++;
        grid_sync(nbar);
    }
}

// =======================================================================
// launch
// =======================================================================
extern "C" void kernel_launch(void* const* d_in, const int* in_sizes, int n_in,
                              void* d_out, int out_size) {
    const float* x  = (const float*)d_in[0];
    const float* Wi = (const float*)d_in[1];
    const float* Wh = (const float*)d_in[2];
    const float* b  = (const float*)d_in[3];
    float* out = (float*)d_out;

    cudaFuncSetAttribute(lstm_main, cudaFuncAttributeMaxDynamicSharedMemorySize, SM_TOTAL);

    minit_kernel<<<64, 256>>>(b);
    wconv_kernel<<<dim3(KTOT / 32, GATES / 32, NLAYER), dim3(32, 32)>>>(Wi, Wh);
    iconv_kernel<<<(NSTEP * BATCH * HID + 255) / 256, 256>>>(x);
    lstm_main<<<NCTA, NTHR, SM_TOTAL>>>(out, out_size);
}

// round 17
// speedup vs baseline: 2.0287x; 1.0592x over previous
#include <cuda_runtime.h>
#include <cuda_bf16.h>
#include <cstdint>
#include <math.h>

// ---------------- problem constants ----------------
#define NLAYER 4
#define HID    1024
#define BATCH  64
#define NSTEP  128
#define GATES  4096            // 4*HID
#define KTOT   2048            // x-part (1024) + h-part (1024)
#define BH     (BATCH * HID)
#define NDIAG  (NSTEP + NLAYER - 1)   // 131 wavefront diagonals

// ---------------- kernel config --------------------
#define NCTA   128             // 4 layers x 32 col-blocks; 1 CTA/SM -> barrier safe
#define NTHR   512             // 16 warps: 2(M,m32) x 4(N,n32) x 2(K-split)
#define NT     128             // permuted gate columns per CTA (32 h-cols x 4 gates)
#define KC     64              // K per pipeline chunk
#define NCHUNK (KTOT / KC)     // 32
#define NSTAGE 4
#define LDA    72              // padded smem row stride (bf16) -> conflict-free ldsm
#define LDC    132             // gates smem row stride (floats)

// smem stage layout (bytes)
#define ST_AHI   0
#define ST_ALO   9216          // 64*72*2
#define ST_WHI   18432
#define ST_WLO   36864         // + 128*72*2
#define ST_BYTES 55296
// 2 gate partial buffers (64 x 132 floats = 33792 B each) overlap stages 0-1
// (last stage-0/1 reads at c=28/29; fenced by the c=30/31 syncs).
#define SM_GS0   0
#define SM_GS1   33792
#define SM_BIAS  (NSTAGE * ST_BYTES)       // 221184
#define SM_TOTAL (SM_BIAS + NT * 4)        // 221696

// ---------------- device scratch (allocation-free rule) ----------------
__device__ __nv_bfloat16 g_Whi[NLAYER][GATES][KTOT];   // [l][np][k], k contiguous
__device__ __nv_bfloat16 g_Wlo[NLAYER][GATES][KTOT];
__device__ __nv_bfloat16 g_Xhi[NSTEP][BATCH][HID];
__device__ __nv_bfloat16 g_Xlo[NSTEP][BATCH][HID];
__device__ __nv_bfloat16 g_Hhi[NLAYER][2][BATCH][HID]; // ping-pong on step parity
__device__ __nv_bfloat16 g_Hlo[NLAYER][2][BATCH][HID];
__device__ float         g_bias[NLAYER][GATES];        // permuted
__device__ unsigned      g_bar_cnt;
__device__ unsigned      g_bar_sense;

// =======================================================================
// conversion / init kernels (rerun each launch; deterministic)
// =======================================================================

__global__ void wconv_kernel(const float* __restrict__ Wi, const float* __restrict__ Wh) {
    __shared__ float s[32][33];
    int l  = blockIdx.z;
    int k0 = blockIdx.x * 32;
    int n0 = blockIdx.y * 32;
    int tx = threadIdx.x, ty = threadIdx.y;

    int k = k0 + ty, n = n0 + tx;
    const float* src = (k < HID)
        ? (Wi + ((size_t)l * HID + k) * GATES + n)
        : (Wh + ((size_t)l * HID + (k - HID)) * GATES + n);
    s[ty][tx] = *src;
    __syncthreads();

    float v  = s[tx][ty];
    int   nn = n0 + ty;
    int   np = 4 * (nn & (HID - 1)) + (nn >> 10);
    __nv_bfloat16 hi = __float2bfloat16(v);
    __nv_bfloat16 lo = __float2bfloat16(v - __bfloat162float(hi));
    g_Whi[l][np][k0 + tx] = hi;
    g_Wlo[l][np][k0 + tx] = lo;
}

__global__ void iconv_kernel(const float* __restrict__ x) {
    size_t i = (size_t)blockIdx.x * blockDim.x + threadIdx.x;
    if (i < (size_t)NSTEP * BATCH * HID) {
        float v = x[i];
        __nv_bfloat16 hi = __float2bfloat16(v);
        __nv_bfloat16 lo = __float2bfloat16(v - __bfloat162float(hi));
        ((__nv_bfloat16*)g_Xhi)[i] = hi;
        ((__nv_bfloat16*)g_Xlo)[i] = lo;
    }
}

__global__ void minit_kernel(const float* __restrict__ b) {
    int i = blockIdx.x * blockDim.x + threadIdx.x;
    if (i < NLAYER * GATES) {
        int l  = i >> 12;
        int n  = i & (GATES - 1);
        int np = 4 * (n & (HID - 1)) + (n >> 10);
        g_bias[l][np] = b[i];
    }
    const int hn = NLAYER * 2 * BATCH * HID;
    for (int j = i; j < hn; j += gridDim.x * blockDim.x) {
        ((__nv_bfloat16*)g_Hhi)[j] = __float2bfloat16(0.f);
        ((__nv_bfloat16*)g_Hlo)[j] = __float2bfloat16(0.f);
    }
    if (i == 0) { g_bar_cnt = 0; g_bar_sense = 0; }
}

// =======================================================================
// persistent LSTM kernel (layer wavefront, 4-stage pipeline)
// =======================================================================

__device__ __forceinline__ void cp16(uint32_t dst, const void* src) {
    asm volatile("cp.async.cg.shared.global [%0], [%1], 16;\n" :: "r"(dst), "l"(src));
}
__device__ __forceinline__ void cp_commit() { asm volatile("cp.async.commit_group;\n"); }
template <int N> __device__ __forceinline__ void cp_wait() {
    asm volatile("cp.async.wait_group %0;\n" :: "n"(N));
}
__device__ __forceinline__ void ldsm4(uint32_t* r, uint32_t addr) {
    asm volatile("ldmatrix.sync.aligned.m8n8.x4.shared.b16 {%0,%1,%2,%3}, [%4];\n"
                 : "=r"(r[0]), "=r"(r[1]), "=r"(r[2]), "=r"(r[3]) : "r"(addr));
}
__device__ __forceinline__ void mma16816(float* c, const uint32_t* a, const uint32_t* b) {
    asm volatile(
        "mma.sync.aligned.m16n8k16.row.col.f32.bf16.bf16.f32 "
        "{%0,%1,%2,%3}, {%4,%5,%6,%7}, {%8,%9}, {%0,%1,%2,%3};\n"
        : "+f"(c[0]), "+f"(c[1]), "+f"(c[2]), "+f"(c[3])
        : "r"(a[0]), "r"(a[1]), "r"(a[2]), "r"(a[3]), "r"(b[0]), "r"(b[1]));
}

__device__ __forceinline__ void grid_sync(unsigned nbar) {
    __threadfence();
    __syncthreads();
    if (threadIdx.x == 0) {
        if (atomicAdd(&g_bar_cnt, 1) == NCTA - 1) {
            g_bar_cnt = 0;
            __threadfence();
            atomicExch(&g_bar_sense, nbar);
        } else {
            while (*(volatile unsigned*)&g_bar_sense < nbar) __nanosleep(64);
            __threadfence();
        }
    }
    __syncthreads();
}

// 3072 x 16B units per KC=64 chunk:
//   A hi/lo: 2 planes * 64 rows * 8 segs  = 1024 units
//   W hi/lo: 2 planes * 128 rows * 8 segs = 2048 units
__device__ __forceinline__ void load_chunk(
    uint32_t stg, int kg0,
    const __nv_bfloat16* __restrict__ A1h, const __nv_bfloat16* __restrict__ A1l,
    const __nv_bfloat16* __restrict__ A2h, const __nv_bfloat16* __restrict__ A2l,
    const __nv_bfloat16* __restrict__ Wh_, const __nv_bfloat16* __restrict__ Wl_,
    int tid)
{
    const __nv_bfloat16* Ah; const __nv_bfloat16* Al; int ko;
    if (kg0 < HID) { Ah = A1h; Al = A1l; ko = kg0; }
    else           { Ah = A2h; Al = A2l; ko = kg0 - HID; }
#pragma unroll
    for (int ii = 0; ii < 6; ii++) {
        int u = tid + ii * NTHR;
        if (u < 1024) {
            int plane = u >> 9, v = u & 511, row = v >> 3, seg = v & 7;
            const __nv_bfloat16* src = (plane ? Al : Ah) + row * HID + ko + seg * 8;
            uint32_t dst = stg + (plane ? ST_ALO : ST_AHI) + (uint32_t)(row * LDA + seg * 8) * 2;
            cp16(dst, src);
        } else {
            int w = u - 1024;
            int plane = w >> 10, v = w & 1023, row = v >> 3, seg = v & 7;
            const __nv_bfloat16* src = (plane ? Wl_ : Wh_) + row * KTOT + kg0 + seg * 8;
            uint32_t dst = stg + (plane ? ST_WLO : ST_WHI) + (uint32_t)(row * LDA + seg * 8) * 2;
            cp16(dst, src);
        }
    }
}

__device__ __forceinline__ float sigmoidf_(float x) { return 1.f / (1.f + expf(-x)); }

__global__ void __launch_bounds__(NTHR, 1)
lstm_main(float* __restrict__ out, int out_floats) {
    extern __shared__ char smem[];
    const uint32_t sbase = (uint32_t)__cvta_generic_to_shared(smem);
    const int tid  = threadIdx.x;
    const int bid  = blockIdx.x;
    const int lane = tid & 31, warp = tid >> 5;
    const int kiB  = warp & 1;                 // K half (4 k16-slices -> 2 each)
    const int njB  = (warp >> 1) & 3;          // N tile: cols [njB*32, njB*32+32)
    const int miB  = warp >> 3;                // M half: rows [miB*32, miB*32+32)

    const int l_own = bid >> 5;                // this CTA's layer
    const int cb    = bid & 31;                // column block
    const int np0   = cb * NT;                 // gate cols [np0, np0+128)

    float* bias_s = (float*)(smem + SM_BIAS);
    for (int i = tid; i < NT; i += NTHR)
        bias_s[i] = g_bias[l_own][np0 + i];

    // cell-update mapping: thread owns rows row_u, 4 local h-cols hb..hb+3
    const int row_u = tid >> 3, hb = (tid & 7) * 4;
    float cst[4];
#pragma unroll
    for (int e = 0; e < 4; e++) cst[e] = 0.f;

    const __nv_bfloat16* Wh_ = &g_Whi[l_own][np0][0];
    const __nv_bfloat16* Wl_ = &g_Wlo[l_own][np0][0];

    __syncthreads();
    unsigned nbar = 0;

    for (int d = 0; d < NDIAG; d++) {
        const int t = d - l_own;
        if (t >= 0 && t < NSTEP) {
            const int par = t & 1, prv = par ^ 1;
            const __nv_bfloat16* A1h = (l_own == 0) ? &g_Xhi[t][0][0] : &g_Hhi[l_own - 1][par][0][0];
            const __nv_bfloat16* A1l = (l_own == 0) ? &g_Xlo[t][0][0] : &g_Hlo[l_own - 1][par][0][0];
            const __nv_bfloat16* A2h = &g_Hhi[l_own][prv][0][0];
            const __nv_bfloat16* A2l = &g_Hlo[l_own][prv][0][0];

            float acc[2][4][4];
#pragma unroll
            for (int f = 0; f < 2; f++)
#pragma unroll
                for (int j = 0; j < 4; j++)
#pragma unroll
                    for (int e = 0; e < 4; e++) acc[f][j][e] = 0.f;

            load_chunk(sbase + 0 * ST_BYTES, 0 * KC, A1h, A1l, A2h, A2l, Wh_, Wl_, tid); cp_commit();
            load_chunk(sbase + 1 * ST_BYTES, 1 * KC, A1h, A1l, A2h, A2l, Wh_, Wl_, tid); cp_commit();
            load_chunk(sbase + 2 * ST_BYTES, 2 * KC, A1h, A1l, A2h, A2l, Wh_, Wl_, tid); cp_commit();

            for (int c = 0; c < NCHUNK; c++) {
                if (c < NCHUNK - 2)      cp_wait<2>();
                else if (c == NCHUNK - 2) cp_wait<1>();
                else                      cp_wait<0>();
                __syncthreads();
                if (c + 3 < NCHUNK) {
                    load_chunk(sbase + (uint32_t)((c + 3) & 3) * ST_BYTES, (c + 3) * KC,
                               A1h, A1l, A2h, A2l, Wh_, Wl_, tid);
                    cp_commit();
                }
                uint32_t stg = sbase + (uint32_t)(c & 3) * ST_BYTES;

#pragma unroll
                for (int q = 0; q < 2; q++) {
                    int ks = kiB * 2 + q;
                    // A fragments: m32 (2 x m16) x k16 at column ks*16, hi and lo
                    uint32_t ah[2][4], al[2][4];
#pragma unroll
                    for (int f = 0; f < 2; f++) {
                        uint32_t arow = miB * 32 + f * 16 + (lane & 15);
                        uint32_t acol = ks * 16 + (lane >> 4) * 8;
                        uint32_t aaddr = stg + ST_AHI + (arow * LDA + acol) * 2;
                        ldsm4(ah[f], aaddr);
                        ldsm4(al[f], aaddr + (ST_ALO - ST_AHI));
                    }
                    // W fragments: n32 (2 x n16) x k16, hi and lo
                    uint32_t bh[2][4], bl[2][4];
#pragma unroll
                    for (int g = 0; g < 2; g++) {
                        uint32_t brow = njB * 32 + g * 16 + (lane & 7) + ((lane >> 4) & 1) * 8;
                        uint32_t bcol = ks * 16 + ((lane >> 3) & 1) * 8;
                        uint32_t baddr = stg + ST_WHI + (brow * LDA + bcol) * 2;
                        ldsm4(bh[g], baddr);
                        ldsm4(bl[g], baddr + (ST_WLO - ST_WHI));
                    }
#pragma unroll
                    for (int f = 0; f < 2; f++)
#pragma unroll
                        for (int j = 0; j < 4; j++) {
                            uint32_t* bhp = &bh[j >> 1][(j & 1) * 2];
                            uint32_t* blp = &bl[j >> 1][(j & 1) * 2];
                            mma16816(acc[f][j], ah[f], bhp);
                            mma16816(acc[f][j], ah[f], blp);
                            mma16816(acc[f][j], al[f], bhp);
                        }
                }
            }

            // dump partial gates to buffer kiB (overlaps stages 0-1; all reads fenced)
            {
                float* gs = (float*)(smem + (kiB ? SM_GS1 : SM_GS0));
#pragma unroll
                for (int f = 0; f < 2; f++) {
                    int r0 = miB * 32 + f * 16 + (lane >> 2);
#pragma unroll
                    for (int j = 0; j < 4; j++) {
                        int c0 = njB * 32 + j * 8 + (lane & 3) * 2;
                        *(float2*)&gs[(r0    ) * LDC + c0] = make_float2(acc[f][j][0], acc[f][j][1]);
                        *(float2*)&gs[(r0 + 8) * LDC + c0] = make_float2(acc[f][j][2], acc[f][j][3]);
                    }
                }
            }
            __syncthreads();

            // cell update: 4 h-elements per thread; sum 2 K-partials + bias
            {
                const float* g0 = (const float*)(smem + SM_GS0);
                const float* g1 = (const float*)(smem + SM_GS1);
#pragma unroll
                for (int e = 0; e < 4; e++) {
                    int hl = hb + e;
                    float4 p0 = *(const float4*)&g0[row_u * LDC + 4 * hl];
                    float4 p1 = *(const float4*)&g1[row_u * LDC + 4 * hl];
                    float4 bb = *(const float4*)&bias_s[4 * hl];

                    float i0 = p0.x + p1.x + bb.x;
                    float f0 = p0.y + p1.y + bb.y;
                    float gg = p0.z + p1.z + bb.z;
                    float o0 = p0.w + p1.w + bb.w;

                    float cn = sigmoidf_(f0) * cst[e] + sigmoidf_(i0) * tanhf(gg);
                    cst[e] = cn;
                    float h = sigmoidf_(o0) * tanhf(cn);

                    int colg = cb * 32 + hl;
                    __nv_bfloat16 hh = __float2bfloat16(h);
                    __nv_bfloat16 hl16 = __float2bfloat16(h - __bfloat162float(hh));
                    g_Hhi[l_own][par][row_u][colg] = hh;
                    g_Hlo[l_own][par][row_u][colg] = hl16;

                    if (l_own == NLAYER - 1 && t == NSTEP - 1) {
                        int idx = row_u * HID + colg;
                        out[idx] = h;                                       // output
                        if (out_floats >= 2 * BH) out[BH + idx] = h;        // h final
                        if (out_floats >= 3 * BH) out[2 * BH + idx] = cn;   // c final
                    }
                }
            }
        }

        nbar++;
        grid_sync(nbar);
    }
}

// =======================================================================
// launch
// =======================================================================
extern "C" void kernel_launch(void* const* d_in, const int* in_sizes, int n_in,
                              void* d_out, int out_size) {
    const float* x  = (const float*)d_in[0];
    const float* Wi = (const float*)d_in[1];
    const float* Wh = (const float*)d_in[2];
    const float* b  = (const float*)d_in[3];
    float* out = (float*)d_out;

    cudaFuncSetAttribute(lstm_main, cudaFuncAttributeMaxDynamicSharedMemorySize, SM_TOTAL);

    minit_kernel<<<64, 256>>>(b);
    wconv_kernel<<<dim3(KTOT / 32, GATES / 32, NLAYER), dim3(32, 32)>>>(Wi, Wh);
    iconv_kernel<<<(NSTEP * BATCH * HID + 255) / 256, 256>>>(x);
    lstm_main<<<NCTA, NTHR, SM_TOTAL>>>(out, out_size);
}